// round 17
// baseline (speedup 1.0000x reference)
#include <cuda_runtime.h>

// B=32, S=12, F=128, K=8, H=64, C=64, N=512
#define BB    32
#define SEQ   12
#define FF    128
#define KK    8
#define HH    64
#define CC    64
#define NNN   512
#define NCHK  512                    // Wf chunk blocks: (cp = blk>>3, p = blk&7), 16 KB each
#define NEPI  64                     // dedicated epilogue blocks (blk >= 512)
#define NBLK  (NCHK + NEPI)          // 576
#define TPB   256

// Scratch + sync (allocation-free rule: __device__ globals).
// Counters monotonic across graph replays; separate 128B lines.
__device__ float g_part[KK * BB * CC];          // [k][b*64+c] per-k WhO partials (64 KB)
__device__ float g_wpart[8 * CC * CC];          // [p][cp*64+c] per-chunk Wf sums (128 KB)
__device__ __align__(128) unsigned int g_d1[32];    // publish count (element 0)
__device__ __align__(128) unsigned int g_tick[32];  // epilogue tickets (element 0)

__device__ __forceinline__ void spin_until(volatile unsigned int* p, unsigned int target)
{
    while (*p < target) { __nanosleep(32); }
}

__global__ void __launch_bounds__(TPB, 4) gat_fused(
    const float* __restrict__ x,        // (32,12,128)
    const float* __restrict__ W_heads,  // (8,128,64)
    const float* __restrict__ W_out,    // (512,64)
    const float* __restrict__ Wf,       // (64, 512*64)
    const float* __restrict__ bf,       // (64,)
    float* __restrict__ out)            // (32,64)
{
    __shared__ float s_x[FF];
    __shared__ float s_hcat[HH];
    __shared__ float s_p[TPB];
    __shared__ float4 s4[TPB];          // 4 KB
    __shared__ float s_wpart[CC];

    const int blk = blockIdx.x;
    const int t   = threadIdx.x;

    if (blk < NCHK) {
        // ============ Chunk block: Wf 16KB chunk (+ stage-1 if blk<256) ============
        const int cp = blk >> 3, p = blk & 7;
        const bool do_s1 = (blk < BB * KK);
        const int b = blk >> 3, k = blk & 7;       // stage-1 task (valid when do_s1)

        if (do_s1 && t < FF) s_x[t] = x[b * SEQ * FF + (SEQ - 1) * FF + t];

        // ---- front-issue 4 Wf LDG.128 (16 KB chunk: 64 n's) ----
        const float4* src4 = (const float4*)(Wf + (size_t)cp * (NNN * CC) + p * (64 * CC));
        const int c4 = t & 15;
        const int nl = t >> 4;          // 0..15
        float4 v0 = src4[(nl     ) * 16 + c4];
        float4 v1 = src4[(nl + 16) * 16 + c4];
        float4 v2 = src4[(nl + 32) * 16 + c4];
        float4 v3 = src4[(nl + 48) * 16 + c4];

        if (do_s1) {
            __syncthreads();            // s_x ready

            // ---- stage-1 (R8/R14 measured-best): 4 threads per h ----
            {
                const int h  = t >> 2;
                const int fg = t & 3;
                const float* wp = W_heads + (size_t)k * FF * HH + h;
                float acc = 0.f;
                #pragma unroll
                for (int i = 0; i < 32; ++i) {
                    const int f = fg * 32 + i;
                    acc = fmaf(s_x[f], wp[f * HH], acc);
                }
                acc += __shfl_down_sync(0xffffffffu, acc, 2);
                acc += __shfl_down_sync(0xffffffffu, acc, 1);
                if (fg == 0) s_hcat[h] = acc > 0.f ? acc : expm1f(acc);
            }
            __syncthreads();

            // ---- per-k WhO partial: part[c] = sum_h s_hcat[h] * W_out[k*64+h, c] ----
            {
                const int c  = t & 63;
                const int hg = t >> 6;
                const float* wop = W_out + (size_t)(k * HH + hg * 16) * CC + c;
                float acc = 0.f;
                #pragma unroll
                for (int i = 0; i < 16; ++i)
                    acc = fmaf(s_hcat[hg * 16 + i], wop[i * CC], acc);
                s_p[t] = acc;
            }
            __syncthreads();
            if (t < CC)
                g_part[k * (BB * CC) + b * CC + t] =
                    s_p[t] + s_p[t + 64] + s_p[t + 128] + s_p[t + 192];
        }

        // ---- Wf chunk reduce ----
        float4 a;
        a.x = (v0.x + v1.x) + (v2.x + v3.x);
        a.y = (v0.y + v1.y) + (v2.y + v3.y);
        a.z = (v0.z + v1.z) + (v2.z + v3.z);
        a.w = (v0.w + v1.w) + (v2.w + v3.w);
        s4[t] = a;
        __syncthreads();
        if (t < 128) { float4 o = s4[t + 128]; s4[t].x += o.x; s4[t].y += o.y; s4[t].z += o.z; s4[t].w += o.w; }
        __syncthreads();
        if (t < 64)  { float4 o = s4[t + 64];  s4[t].x += o.x; s4[t].y += o.y; s4[t].z += o.z; s4[t].w += o.w; }
        __syncthreads();
        if (t < 16) {
            float4 r = s4[t];
            float4 o1 = s4[t + 16], o2 = s4[t + 32], o3 = s4[t + 48];
            const int base = p * (CC * CC) + cp * CC + 4 * t;
            g_wpart[base + 0] = r.x + o1.x + o2.x + o3.x;
            g_wpart[base + 1] = r.y + o1.y + o2.y + o3.y;
            g_wpart[base + 2] = r.z + o1.z + o2.z + o3.z;
            g_wpart[base + 3] = r.w + o1.w + o2.w + o3.w;
        }

        // ---- publish and exit ----
        __threadfence();
        __syncthreads();
        if (t == 0) atomicAdd(&g_d1[0], 1u);
        return;
    }

    // ============ Epilogue block: one output column cpe ============
    const int cpe = blk - NCHK;         // 0..63

    __shared__ unsigned int s_target;
    if (t == 0) {
        const unsigned int epoch = atomicAdd(&g_tick[0], 1u) / NEPI;
        s_target = (epoch + 1u) * NCHK;
        spin_until(&g_d1[0], s_target);
    }
    __syncthreads();
    __threadfence();

    // ---- assemble full wpart for cpe (8 partials) ----
    if (t < CC) {
        float s = 0.f;
        #pragma unroll
        for (int pp = 0; pp < 8; ++pp)
            s += g_wpart[pp * (CC * CC) + cpe * CC + t];
        s_wpart[t] = s;
    }
    __syncthreads();

    // ---- out[b2,cpe] = bf[cpe] + sum_k sum_c part[k][b2,c] * wpart[c] ----
    {
        const int b2 = t >> 3;          // 0..31
        const int jg = t & 7;           // 8 c's each
        const float4 wa = *(const float4*)(s_wpart + jg * 8);
        const float4 wb = *(const float4*)(s_wpart + jg * 8 + 4);
        float acc = 0.f;
        #pragma unroll
        for (int kk2 = 0; kk2 < KK; ++kk2) {
            const float4* pr = (const float4*)(g_part + kk2 * (BB * CC) + b2 * CC + jg * 8);
            const float4 r0 = pr[0], r1 = pr[1];
            acc += r0.x * wa.x + r0.y * wa.y + r0.z * wa.z + r0.w * wa.w
                 + r1.x * wb.x + r1.y * wb.y + r1.z * wb.z + r1.w * wb.w;
        }
        acc += __shfl_down_sync(0xffffffffu, acc, 4);
        acc += __shfl_down_sync(0xffffffffu, acc, 2);
        acc += __shfl_down_sync(0xffffffffu, acc, 1);
        if (jg == 0) out[b2 * CC + cpe] = bf[cpe] + acc;   // direct store — no atomics
    }
}

extern "C" void kernel_launch(void* const* d_in, const int* in_sizes, int n_in,
                              void* d_out, int out_size)
{
    const float* x       = (const float*)d_in[0];
    const float* W_heads = (const float*)d_in[1];
    // d_in[2], d_in[3]: a1_heads/a2_heads — drop out (uniform softmax)
    const float* W_out   = (const float*)d_in[4];
    // d_in[5], d_in[6]: a1_out/a2_out — drop out
    const float* Wf      = (const float*)d_in[7];
    const float* bf      = (const float*)d_in[8];
    float* out           = (float*)d_out;

    gat_fused<<<NBLK, TPB>>>(x, W_heads, W_out, Wf, bf, out);
}